// round 14
// baseline (speedup 1.0000x reference)
#include <cuda_runtime.h>
#include <math.h>

#define N_NODES   100000
#define E_EDGES   3200000
#define FIN       512
#define F1        16
#define F2        40
#define SCAN_B    1024
#define NBLK      ((N_NODES + SCAN_B - 1) / SCAN_B)   // 98

// ---------------- scratch (no cudaMalloc allowed) ----------------
// Device symbols referenced ONLY from device code.
__device__ int    g_nz;                   // 0 => int64 edges, 1 => int32
__device__ int    g_done;                 // scan: blocks finished phase 1
__device__ int    g_flag;                 // scan: block offsets published
__device__ int    g_cnt   [N_NODES];      // in-degree (excluding self loop)
__device__ int    g_fill  [N_NODES];      // CSR fill cursors
__device__ int    g_rowptr[N_NODES + 1];
__device__ int    g_blksum[128];
__device__ int    g_blkoff[128];
__device__ float  g_dinv  [N_NODES];
__device__ int    g_dst   [E_EDGES];
__device__ int    g_srcT  [E_EDGES];      // src staging
__device__ int    g_csrc  [E_EDGES];      // src ids grouped by dst (CSR)
__device__ float4 g_raw   [N_NODES * 4];  // x @ W1, unscaled (gemm output)
__device__ float4 g_hs    [N_NODES * 4];  // layer-1 features, pre-scaled by dinv
__device__ float4 g_hs2   [N_NODES * 4];  // layer-2 features, pre-scaled by dinv

// ---------------- K0: zero counters + dtype probe (fused) ----------------
__global__ void k_zero(const unsigned* __restrict__ I, int n) {
    int i = blockIdx.x * blockDim.x + threadIdx.x;
    if (i == 0) { g_done = 0; g_flag = 0; }
    if (i < n) { g_cnt[i] = 0; g_fill[i] = 0; }
    if (blockIdx.x == 0) {
        __shared__ int f;
        if (threadIdx.x == 0) f = 0;
        __syncthreads();
        // int64 little-endian ids < 2^17 => odd 32-bit words all zero.
        unsigned w = I[2 * (threadIdx.x * 1001) + 1]
                   | I[2 * (threadIdx.x * 4001) + 1];
        if (w != 0u) f = 1;        // benign race
        __syncthreads();
        if (threadIdx.x == 0) g_nz = f;
    }
}

// ---------------- K1: edges -> int32 staging, histogram in-degree ----------------
__global__ void k_edge_prep(const unsigned* __restrict__ I, int E) {
    int e = blockIdx.x * blockDim.x + threadIdx.x;
    if (e >= E) return;
    int s, d;
    if (g_nz == 0) {            // int64: take low words
        s = (int)I[2 * e];
        d = (int)I[2 * (E + e)];
    } else {                    // int32
        s = (int)I[e];
        d = (int)I[E + e];
    }
    if ((unsigned)s >= (unsigned)N_NODES) s = 0;   // defensive clamp
    if ((unsigned)d >= (unsigned)N_NODES) d = 0;
    g_srcT[e] = s;
    g_dst [e] = d;
    atomicAdd(&g_cnt[d], 1);    // unused return -> fire-and-forget RED
}

// ---------------- K2: single-kernel exclusive scan + dinv ----------------
__global__ __launch_bounds__(SCAN_B) void k_scan(int n, int E) {
    __shared__ int sm[SCAN_B];
    __shared__ int sm2[128];
    const int t   = threadIdx.x;
    const int bid = blockIdx.x;
    const int i   = bid * SCAN_B + t;

    int x = (i < n) ? g_cnt[i] : 0;
    sm[t] = x;
    __syncthreads();
    for (int off = 1; off < SCAN_B; off <<= 1) {
        int v = (t >= off) ? sm[t - off] : 0;
        __syncthreads();
        sm[t] += v;
        __syncthreads();
    }
    int excl = sm[t] - x;                       // exclusive within block
    if (t == SCAN_B - 1) g_blksum[bid] = sm[t];
    __threadfence();
    if (t == SCAN_B - 1) atomicAdd(&g_done, 1);

    if (bid == 0) {
        if (t == 0) {
            while (atomicAdd(&g_done, 0) < gridDim.x) __nanosleep(40);
        }
        __syncthreads();
        int y = (t < 128 && t < (int)gridDim.x) ? g_blksum[t] : 0;
        if (t < 128) sm2[t] = y;
        __syncthreads();
        for (int off = 1; off < 128; off <<= 1) {
            int v = (t >= off && t < 128) ? sm2[t - off] : 0;
            __syncthreads();
            if (t < 128) sm2[t] += v;
            __syncthreads();
        }
        if (t < 128) g_blkoff[t] = sm2[t] - y;  // exclusive block offsets
        __threadfence();
        __syncthreads();
        if (t == 0) atomicExch(&g_flag, 1);
    } else {
        if (t == 0) {
            while (atomicAdd(&g_flag, 0) == 0) __nanosleep(40);
        }
        __syncthreads();
    }

    if (i < n) {
        g_rowptr[i] = excl + g_blkoff[bid];
        g_dinv[i]   = rsqrtf((float)(x + 1));   // +1 self loop
    }
    if (bid == 0 && t == 0) g_rowptr[n] = E;
}

// ---------------- K3: CSR fill (scalar int atomics only) ----------------
__global__ void k_fill(int E) {
    int e = blockIdx.x * blockDim.x + threadIdx.x;
    if (e >= E) return;
    int d = g_dst[e];
    int pos = g_rowptr[d] + atomicAdd(&g_fill[d], 1);
    if ((unsigned)pos >= (unsigned)E_EDGES) pos = 0;   // defensive clamp
    g_csrc[pos] = g_srcT[e];
}

// ---------------- K4: raw = x @ W1 (fp32, overlaps CSR build) ----------------
#define G_ROWS 128
#define G_KC   64
#define G_XS   68   // padded stride (floats)

__global__ __launch_bounds__(256) void k_gemm1(
    const float* __restrict__ x, const float* __restrict__ W1, int n)
{
    __shared__ float Wsm[G_KC * 16];        // 4 KB
    __shared__ float xsm[G_ROWS * G_XS];    // 34 KB
    const int tid  = threadIdx.x;
    const int row0 = blockIdx.x * G_ROWS;
    const int rg   = tid >> 2;              // 0..63 -> rows 2rg,2rg+1
    const int cg   = tid & 3;               // cols 4cg..4cg+3
    const int r0s  = (rg * 2) * G_XS;
    const int r1s  = r0s + G_XS;

    float4 acc0 = make_float4(0.f, 0.f, 0.f, 0.f);
    float4 acc1 = make_float4(0.f, 0.f, 0.f, 0.f);

    const int f4c = tid & 15;               // x-tile loader: 16 f4 cols
    const int rof = tid >> 4;               // 16 rows per pass

    for (int kc = 0; kc < FIN; kc += G_KC) {
        __syncthreads();
        ((float4*)Wsm)[tid] = ((const float4*)W1)[kc * 4 + tid];
        #pragma unroll
        for (int p = 0; p < 8; p++) {
            int r = p * 16 + rof;
            int gr = row0 + r; if (gr >= n) gr = n - 1;   // clamp (safe re-read)
            float4 v = *(const float4*)(x + (size_t)gr * FIN + kc + f4c * 4);
            *(float4*)(xsm + r * G_XS + f4c * 4) = v;
        }
        __syncthreads();
        #pragma unroll 16
        for (int k = 0; k < G_KC; k++) {
            float4 w4 = *(const float4*)(Wsm + k * 16 + cg * 4);
            float x0 = xsm[r0s + k];
            float x1 = xsm[r1s + k];
            acc0.x = fmaf(x0, w4.x, acc0.x);
            acc0.y = fmaf(x0, w4.y, acc0.y);
            acc0.z = fmaf(x0, w4.z, acc0.z);
            acc0.w = fmaf(x0, w4.w, acc0.w);
            acc1.x = fmaf(x1, w4.x, acc1.x);
            acc1.y = fmaf(x1, w4.y, acc1.y);
            acc1.z = fmaf(x1, w4.z, acc1.z);
            acc1.w = fmaf(x1, w4.w, acc1.w);
        }
    }
    int r0 = row0 + 2 * rg;
    if (r0 < n) g_raw[(size_t)r0 * 4 + cg] = acc0;
    int r1 = r0 + 1;
    if (r1 < n) g_raw[(size_t)r1 * 4 + cg] = acc1;
}

// ---------------- K4b: hs = raw * dinv[row] (side stream; overlaps fill) ----------------
__global__ void k_scale(int n) {
    int idx = blockIdx.x * blockDim.x + threadIdx.x;   // over n*4 quarters
    if (idx >= n * 4) return;
    float di = g_dinv[idx >> 2];
    float4 v = g_raw[idx];
    g_hs[idx] = make_float4(v.x * di, v.y * di, v.z * di, v.w * di);
}

// ---------------- K5: layer-1 CSR gather (proven R10 body, phase-0 only) ----------------
// Warp per node. Lane = (edge slot eq 0..7) x (feature quarter q 0..3).
// out = relu((acc+self)*dinv + b1) * dinv -> g_hs2
__global__ __launch_bounds__(256) void k_gather1(
    const float* __restrict__ b1, int n)
{
    int wid = (blockIdx.x * blockDim.x + threadIdx.x) >> 5;
    if (wid >= n) return;
    int lane = threadIdx.x & 31;
    int q  = lane & 3;
    int eq = lane >> 2;
    int start = g_rowptr[wid];
    int end   = g_rowptr[wid + 1];
    float4 acc = make_float4(0.f, 0.f, 0.f, 0.f);
    for (int e = start + eq; e < end; e += 8) {
        int s = g_csrc[e];
        float4 v = g_hs[(size_t)s * 4 + q];
        acc.x += v.x; acc.y += v.y; acc.z += v.z; acc.w += v.w;
    }
    #pragma unroll
    for (int off = 4; off < 32; off <<= 1) {
        acc.x += __shfl_xor_sync(0xffffffffu, acc.x, off);
        acc.y += __shfl_xor_sync(0xffffffffu, acc.y, off);
        acc.z += __shfl_xor_sync(0xffffffffu, acc.z, off);
        acc.w += __shfl_xor_sync(0xffffffffu, acc.w, off);
    }
    if (eq == 0) {
        float4 self = g_hs[(size_t)wid * 4 + q];
        acc.x += self.x; acc.y += self.y; acc.z += self.z; acc.w += self.w;
        float di = g_dinv[wid];
        float4 b = ((const float4*)b1)[q];
        acc.x = fmaxf(fmaf(acc.x, di, b.x), 0.f) * di;
        acc.y = fmaxf(fmaf(acc.y, di, b.y), 0.f) * di;
        acc.z = fmaxf(fmaf(acc.z, di, b.z), 0.f) * di;
        acc.w = fmaxf(fmaf(acc.w, di, b.w), 0.f) * di;
        g_hs2[(size_t)wid * 4 + q] = acc;
    }
}

// ---------------- K6: fused layer-2 gather + W2 GEMM + log_softmax ----------------
// Identical gather body; then the warp finishes its node in-register:
// broadcast the 16 features, each lane computes output cols lane and lane+32,
// warp-reduce logsumexp, coalesced 160B/row store. Replaces gather2 + k_final
// and the 6.4MB g_agg round-trip.
__global__ __launch_bounds__(256) void k_gather2f(
    const float* __restrict__ W2, const float* __restrict__ b2,
    float* __restrict__ out, int n)
{
    __shared__ float Wsm[F1 * F2];      // 640 floats
    __shared__ float bsm[F2];
    int tid = threadIdx.x;
    for (int i = tid; i < F1 * F2; i += 256) Wsm[i] = W2[i];
    if (tid < F2) bsm[tid] = b2[tid];
    __syncthreads();

    int wid = (blockIdx.x * blockDim.x + tid) >> 5;
    if (wid >= n) return;
    int lane = tid & 31;
    int q  = lane & 3;
    int eq = lane >> 2;
    int start = g_rowptr[wid];
    int end   = g_rowptr[wid + 1];
    float4 acc = make_float4(0.f, 0.f, 0.f, 0.f);
    for (int e = start + eq; e < end; e += 8) {
        int s = g_csrc[e];
        float4 v = g_hs2[(size_t)s * 4 + q];
        acc.x += v.x; acc.y += v.y; acc.z += v.z; acc.w += v.w;
    }
    #pragma unroll
    for (int off = 4; off < 32; off <<= 1) {
        acc.x += __shfl_xor_sync(0xffffffffu, acc.x, off);
        acc.y += __shfl_xor_sync(0xffffffffu, acc.y, off);
        acc.z += __shfl_xor_sync(0xffffffffu, acc.z, off);
        acc.w += __shfl_xor_sync(0xffffffffu, acc.w, off);
    }
    // Every lane holds the q-total for q = lane&3. Add self, scale by dinv.
    float4 self = g_hs2[(size_t)wid * 4 + q];
    float di = g_dinv[wid];
    acc.x = (acc.x + self.x) * di;
    acc.y = (acc.y + self.y) * di;
    acc.z = (acc.z + self.z) * di;
    acc.w = (acc.w + self.w) * di;

    // Broadcast the 16 features (lanes 0..3 hold q=0..3).
    float a[F1];
    #pragma unroll
    for (int qq = 0; qq < 4; qq++) {
        a[4 * qq + 0] = __shfl_sync(0xffffffffu, acc.x, qq);
        a[4 * qq + 1] = __shfl_sync(0xffffffffu, acc.y, qq);
        a[4 * qq + 2] = __shfl_sync(0xffffffffu, acc.z, qq);
        a[4 * qq + 3] = __shfl_sync(0xffffffffu, acc.w, qq);
    }

    // Lane computes output columns lane and lane+32 (latter only lanes 0..7).
    int j0 = lane, j1 = lane + 32;
    bool has1 = (j1 < F2);
    float o0 = bsm[j0];
    float o1 = has1 ? bsm[j1] : 0.f;
    #pragma unroll
    for (int k = 0; k < F1; k++) {
        o0 = fmaf(a[k], Wsm[k * F2 + j0], o0);
        if (has1) o1 = fmaf(a[k], Wsm[k * F2 + j1], o1);
    }
    float m = has1 ? fmaxf(o0, o1) : o0;
    #pragma unroll
    for (int off = 1; off < 32; off <<= 1)
        m = fmaxf(m, __shfl_xor_sync(0xffffffffu, m, off));
    float sum = expf(o0 - m) + (has1 ? expf(o1 - m) : 0.f);
    #pragma unroll
    for (int off = 1; off < 32; off <<= 1)
        sum += __shfl_xor_sync(0xffffffffu, sum, off);
    float lse = m + logf(sum);
    out[(size_t)wid * F2 + j0] = o0 - lse;
    if (has1) out[(size_t)wid * F2 + j1] = o1 - lse;
}

// ---------------- launch ----------------
extern "C" void kernel_launch(void* const* d_in, const int* in_sizes, int n_in,
                              void* d_out, int out_size) {
    // Identify inputs by element count (immune to metadata ordering):
    const float* x  = nullptr; const void* ei = nullptr;
    const float* W1 = nullptr; const float* b1 = nullptr;
    const float* W2 = nullptr; const float* b2 = nullptr;
    for (int i = 0; i < n_in; i++) {
        switch (in_sizes[i]) {
            case 51200000: x  = (const float*)d_in[i]; break;
            case 6400000:  ei = d_in[i];               break;
            case 8192:     W1 = (const float*)d_in[i]; break;
            case 16:       b1 = (const float*)d_in[i]; break;
            case 640:      W2 = (const float*)d_in[i]; break;
            case 40:       b2 = (const float*)d_in[i]; break;
            default: break;
        }
    }
    if (!x)  x  = (const float*)d_in[0];
    if (!ei) ei = d_in[1];
    if (!W1) W1 = (const float*)d_in[2];
    if (!b1) b1 = (const float*)d_in[3];
    if (!W2) W2 = (const float*)d_in[4];
    if (!b2) b2 = (const float*)d_in[5];

    const int N = N_NODES;
    const int E = E_EDGES;
    float* out = (float*)d_out;
    const unsigned* eiw = (const unsigned*)ei;

    // One-time side stream + fork/join events (not device memory).
    static cudaStream_t s1 = nullptr;
    static cudaEvent_t  evFork = nullptr, evScan = nullptr, evJoin = nullptr;
    if (!s1) {
        cudaStreamCreateWithFlags(&s1, cudaStreamNonBlocking);
        cudaEventCreateWithFlags(&evFork, cudaEventDisableTiming);
        cudaEventCreateWithFlags(&evScan, cudaEventDisableTiming);
        cudaEventCreateWithFlags(&evJoin, cudaEventDisableTiming);
    }

    // Fork: gemm1 (FMA-bound) on side stream, overlapping the CSR build.
    cudaEventRecord(evFork, 0);
    cudaStreamWaitEvent(s1, evFork, 0);
    k_gemm1<<<(N + G_ROWS - 1) / G_ROWS, 256, 0, s1>>>(x, W1, N);

    // CSR build chain on the main stream.
    k_zero     <<<(N + 255) / 256, 256>>>(eiw, N);
    k_edge_prep<<<(E + 255) / 256, 256>>>(eiw, E);
    k_scan     <<<NBLK, SCAN_B>>>(N, E);
    cudaEventRecord(evScan, 0);

    // Side stream: scale = raw * dinv (needs gemm + scan), overlaps fill.
    cudaStreamWaitEvent(s1, evScan, 0);
    k_scale<<<(N * 4 + 255) / 256, 256, 0, s1>>>(N);
    cudaEventRecord(evJoin, s1);

    // Main: fill, then join and aggregate.
    k_fill     <<<(E + 255) / 256, 256>>>(E);
    cudaStreamWaitEvent(0, evJoin, 0);
    k_gather1  <<<(N * 32 + 255) / 256, 256>>>(b1, N);
    k_gather2f <<<(N * 32 + 255) / 256, 256>>>(W2, b2, out, N);
}

// round 15
// speedup vs baseline: 1.5162x; 1.5162x over previous
#include <cuda_runtime.h>
#include <math.h>

#define N_NODES   100000
#define E_EDGES   3200000
#define FIN       512
#define F1        16
#define F2        40
#define SCAN_B    1024
#define NBLK      ((N_NODES + SCAN_B - 1) / SCAN_B)   // 98

// ---------------- scratch (no cudaMalloc allowed) ----------------
// Device symbols referenced ONLY from device code.
__device__ int    g_nz;                   // 0 => int64 edges, 1 => int32
__device__ int    g_cnt   [N_NODES];      // in-degree (excluding self loop)
__device__ int    g_fill  [N_NODES];      // CSR fill cursors
__device__ int    g_rowptr[N_NODES + 1];
__device__ int    g_blksum[128];
__device__ int    g_blkoff[128];
__device__ float  g_dinv  [N_NODES];
__device__ int    g_dst   [E_EDGES];
__device__ int    g_srcT  [E_EDGES];      // src staging
__device__ int    g_csrc  [E_EDGES];      // src ids grouped by dst (CSR)
__device__ float4 g_raw   [N_NODES * 4];  // x @ W1, unscaled (gemm output)
__device__ float4 g_hs    [N_NODES * 4];  // layer-1 features, pre-scaled by dinv
__device__ float4 g_hs2   [N_NODES * 4];  // layer-2 features, pre-scaled by dinv

// ---------------- K0: zero counters + dtype probe (fused) ----------------
__global__ void k_zero(const unsigned* __restrict__ I, int n) {
    int i = blockIdx.x * blockDim.x + threadIdx.x;
    if (i < n) { g_cnt[i] = 0; g_fill[i] = 0; }
    if (blockIdx.x == 0) {
        __shared__ int f;
        if (threadIdx.x == 0) f = 0;
        __syncthreads();
        // int64 little-endian ids < 2^17 => odd 32-bit words all zero.
        unsigned w = I[2 * (threadIdx.x * 1001) + 1]
                   | I[2 * (threadIdx.x * 4001) + 1];
        if (w != 0u) f = 1;        // benign race
        __syncthreads();
        if (threadIdx.x == 0) g_nz = f;
    }
}

// ---------------- K1: edges -> int32 staging, histogram in-degree ----------------
__global__ void k_edge_prep(const unsigned* __restrict__ I, int E) {
    int e = blockIdx.x * blockDim.x + threadIdx.x;
    if (e >= E) return;
    int s, d;
    if (g_nz == 0) {            // int64: take low words
        s = (int)I[2 * e];
        d = (int)I[2 * (E + e)];
    } else {                    // int32
        s = (int)I[e];
        d = (int)I[E + e];
    }
    if ((unsigned)s >= (unsigned)N_NODES) s = 0;   // defensive clamp
    if ((unsigned)d >= (unsigned)N_NODES) d = 0;
    g_srcT[e] = s;
    g_dst [e] = d;
    atomicAdd(&g_cnt[d], 1);    // unused return -> fire-and-forget RED
}

// ---------------- K2a/b/c: exclusive scan of g_cnt -> g_rowptr (deterministic,
// no grid-sync: safe to overlap with gemm1 regardless of SM residency) --------
__global__ void k_scanA(int n) {
    __shared__ int sm[SCAN_B];
    int t = threadIdx.x;
    int i = blockIdx.x * SCAN_B + t;
    int x = (i < n) ? g_cnt[i] : 0;
    sm[t] = x;
    __syncthreads();
    for (int off = 1; off < SCAN_B; off <<= 1) {
        int v = (t >= off) ? sm[t - off] : 0;
        __syncthreads();
        sm[t] += v;
        __syncthreads();
    }
    if (i < n) g_rowptr[i] = sm[t] - x;          // exclusive, per-block partial
    if (t == SCAN_B - 1) g_blksum[blockIdx.x] = sm[t];
}
__global__ void k_scanB() {
    __shared__ int sm[128];
    int t = threadIdx.x;
    int x = (t < NBLK) ? g_blksum[t] : 0;
    sm[t] = x;
    __syncthreads();
    for (int off = 1; off < 128; off <<= 1) {
        int v = (t >= off) ? sm[t - off] : 0;
        __syncthreads();
        sm[t] += v;
        __syncthreads();
    }
    g_blkoff[t] = sm[t] - x;                     // exclusive block offsets
}
__global__ void k_scanC(int n, int E) {
    int i = blockIdx.x * blockDim.x + threadIdx.x;
    if (i < n) {
        g_rowptr[i] += g_blkoff[i >> 10];
        g_dinv[i] = rsqrtf((float)(g_cnt[i] + 1));   // +1 self loop
    }
    if (i == 0) g_rowptr[n] = E;
}

// ---------------- K3: CSR fill (scalar int atomics only) ----------------
__global__ void k_fill(int E) {
    int e = blockIdx.x * blockDim.x + threadIdx.x;
    if (e >= E) return;
    int d = g_dst[e];
    int pos = g_rowptr[d] + atomicAdd(&g_fill[d], 1);
    if ((unsigned)pos >= (unsigned)E_EDGES) pos = 0;   // defensive clamp
    g_csrc[pos] = g_srcT[e];
}

// ---------------- K4: raw = x @ W1 (fp32, overlaps CSR build) ----------------
#define G_ROWS 128
#define G_KC   64
#define G_XS   68   // padded stride (floats)

__global__ __launch_bounds__(256) void k_gemm1(
    const float* __restrict__ x, const float* __restrict__ W1, int n)
{
    __shared__ float Wsm[G_KC * 16];        // 4 KB
    __shared__ float xsm[G_ROWS * G_XS];    // 34 KB
    const int tid  = threadIdx.x;
    const int row0 = blockIdx.x * G_ROWS;
    const int rg   = tid >> 2;              // 0..63 -> rows 2rg,2rg+1
    const int cg   = tid & 3;               // cols 4cg..4cg+3
    const int r0s  = (rg * 2) * G_XS;
    const int r1s  = r0s + G_XS;

    float4 acc0 = make_float4(0.f, 0.f, 0.f, 0.f);
    float4 acc1 = make_float4(0.f, 0.f, 0.f, 0.f);

    const int f4c = tid & 15;               // x-tile loader: 16 f4 cols
    const int rof = tid >> 4;               // 16 rows per pass

    for (int kc = 0; kc < FIN; kc += G_KC) {
        __syncthreads();
        ((float4*)Wsm)[tid] = ((const float4*)W1)[kc * 4 + tid];
        #pragma unroll
        for (int p = 0; p < 8; p++) {
            int r = p * 16 + rof;
            int gr = row0 + r; if (gr >= n) gr = n - 1;   // clamp (safe re-read)
            float4 v = *(const float4*)(x + (size_t)gr * FIN + kc + f4c * 4);
            *(float4*)(xsm + r * G_XS + f4c * 4) = v;
        }
        __syncthreads();
        #pragma unroll 16
        for (int k = 0; k < G_KC; k++) {
            float4 w4 = *(const float4*)(Wsm + k * 16 + cg * 4);
            float x0 = xsm[r0s + k];
            float x1 = xsm[r1s + k];
            acc0.x = fmaf(x0, w4.x, acc0.x);
            acc0.y = fmaf(x0, w4.y, acc0.y);
            acc0.z = fmaf(x0, w4.z, acc0.z);
            acc0.w = fmaf(x0, w4.w, acc0.w);
            acc1.x = fmaf(x1, w4.x, acc1.x);
            acc1.y = fmaf(x1, w4.y, acc1.y);
            acc1.z = fmaf(x1, w4.z, acc1.z);
            acc1.w = fmaf(x1, w4.w, acc1.w);
        }
    }
    int r0 = row0 + 2 * rg;
    if (r0 < n) g_raw[(size_t)r0 * 4 + cg] = acc0;
    int r1 = r0 + 1;
    if (r1 < n) g_raw[(size_t)r1 * 4 + cg] = acc1;
}

// ---------------- K4b: hs = raw * dinv[row] (side stream; overlaps fill) ----------------
__global__ void k_scale(int n) {
    int idx = blockIdx.x * blockDim.x + threadIdx.x;   // over n*4 quarters
    if (idx >= n * 4) return;
    float di = g_dinv[idx >> 2];
    float4 v = g_raw[idx];
    g_hs[idx] = make_float4(v.x * di, v.y * di, v.z * di, v.w * di);
}

// ---------------- K5: layer-1 CSR gather (proven R10 body, phase-0 only) ----------------
// Warp per node. Lane = (edge slot eq 0..7) x (feature quarter q 0..3).
// out = relu((acc+self)*dinv + b1) * dinv -> g_hs2
__global__ __launch_bounds__(256) void k_gather1(
    const float* __restrict__ b1, int n)
{
    int wid = (blockIdx.x * blockDim.x + threadIdx.x) >> 5;
    if (wid >= n) return;
    int lane = threadIdx.x & 31;
    int q  = lane & 3;
    int eq = lane >> 2;
    int start = g_rowptr[wid];
    int end   = g_rowptr[wid + 1];
    float4 acc = make_float4(0.f, 0.f, 0.f, 0.f);
    for (int e = start + eq; e < end; e += 8) {
        int s = g_csrc[e];
        float4 v = g_hs[(size_t)s * 4 + q];
        acc.x += v.x; acc.y += v.y; acc.z += v.z; acc.w += v.w;
    }
    #pragma unroll
    for (int off = 4; off < 32; off <<= 1) {
        acc.x += __shfl_xor_sync(0xffffffffu, acc.x, off);
        acc.y += __shfl_xor_sync(0xffffffffu, acc.y, off);
        acc.z += __shfl_xor_sync(0xffffffffu, acc.z, off);
        acc.w += __shfl_xor_sync(0xffffffffu, acc.w, off);
    }
    if (eq == 0) {
        float4 self = g_hs[(size_t)wid * 4 + q];
        acc.x += self.x; acc.y += self.y; acc.z += self.z; acc.w += self.w;
        float di = g_dinv[wid];
        float4 b = ((const float4*)b1)[q];
        acc.x = fmaxf(fmaf(acc.x, di, b.x), 0.f) * di;
        acc.y = fmaxf(fmaf(acc.y, di, b.y), 0.f) * di;
        acc.z = fmaxf(fmaf(acc.z, di, b.z), 0.f) * di;
        acc.w = fmaxf(fmaf(acc.w, di, b.w), 0.f) * di;
        g_hs2[(size_t)wid * 4 + q] = acc;
    }
}

// ---------------- K6: fused layer-2 gather + W2 GEMM + log_softmax ----------------
__global__ __launch_bounds__(256) void k_gather2f(
    const float* __restrict__ W2, const float* __restrict__ b2,
    float* __restrict__ out, int n)
{
    __shared__ float Wsm[F1 * F2];      // 640 floats
    __shared__ float bsm[F2];
    int tid = threadIdx.x;
    for (int i = tid; i < F1 * F2; i += 256) Wsm[i] = W2[i];
    if (tid < F2) bsm[tid] = b2[tid];
    __syncthreads();

    int wid = (blockIdx.x * blockDim.x + tid) >> 5;
    if (wid >= n) return;
    int lane = tid & 31;
    int q  = lane & 3;
    int eq = lane >> 2;
    int start = g_rowptr[wid];
    int end   = g_rowptr[wid + 1];
    float4 acc = make_float4(0.f, 0.f, 0.f, 0.f);
    for (int e = start + eq; e < end; e += 8) {
        int s = g_csrc[e];
        float4 v = g_hs2[(size_t)s * 4 + q];
        acc.x += v.x; acc.y += v.y; acc.z += v.z; acc.w += v.w;
    }
    #pragma unroll
    for (int off = 4; off < 32; off <<= 1) {
        acc.x += __shfl_xor_sync(0xffffffffu, acc.x, off);
        acc.y += __shfl_xor_sync(0xffffffffu, acc.y, off);
        acc.z += __shfl_xor_sync(0xffffffffu, acc.z, off);
        acc.w += __shfl_xor_sync(0xffffffffu, acc.w, off);
    }
    // Every lane holds the q-total for q = lane&3. Add self, scale by dinv.
    float4 self = g_hs2[(size_t)wid * 4 + q];
    float di = g_dinv[wid];
    acc.x = (acc.x + self.x) * di;
    acc.y = (acc.y + self.y) * di;
    acc.z = (acc.z + self.z) * di;
    acc.w = (acc.w + self.w) * di;

    // Broadcast the 16 features (lanes 0..3 hold q=0..3).
    float a[F1];
    #pragma unroll
    for (int qq = 0; qq < 4; qq++) {
        a[4 * qq + 0] = __shfl_sync(0xffffffffu, acc.x, qq);
        a[4 * qq + 1] = __shfl_sync(0xffffffffu, acc.y, qq);
        a[4 * qq + 2] = __shfl_sync(0xffffffffu, acc.z, qq);
        a[4 * qq + 3] = __shfl_sync(0xffffffffu, acc.w, qq);
    }

    // Lane computes output columns lane and lane+32 (latter only lanes 0..7).
    int j0 = lane, j1 = lane + 32;
    bool has1 = (j1 < F2);
    float o0 = bsm[j0];
    float o1 = has1 ? bsm[j1] : 0.f;
    #pragma unroll
    for (int k = 0; k < F1; k++) {
        o0 = fmaf(a[k], Wsm[k * F2 + j0], o0);
        if (has1) o1 = fmaf(a[k], Wsm[k * F2 + j1], o1);
    }
    float m = has1 ? fmaxf(o0, o1) : o0;
    #pragma unroll
    for (int off = 1; off < 32; off <<= 1)
        m = fmaxf(m, __shfl_xor_sync(0xffffffffu, m, off));
    float sum = expf(o0 - m) + (has1 ? expf(o1 - m) : 0.f);
    #pragma unroll
    for (int off = 1; off < 32; off <<= 1)
        sum += __shfl_xor_sync(0xffffffffu, sum, off);
    float lse = m + logf(sum);
    out[(size_t)wid * F2 + j0] = o0 - lse;
    if (has1) out[(size_t)wid * F2 + j1] = o1 - lse;
}

// ---------------- launch ----------------
extern "C" void kernel_launch(void* const* d_in, const int* in_sizes, int n_in,
                              void* d_out, int out_size) {
    // Identify inputs by element count (immune to metadata ordering):
    const float* x  = nullptr; const void* ei = nullptr;
    const float* W1 = nullptr; const float* b1 = nullptr;
    const float* W2 = nullptr; const float* b2 = nullptr;
    for (int i = 0; i < n_in; i++) {
        switch (in_sizes[i]) {
            case 51200000: x  = (const float*)d_in[i]; break;
            case 6400000:  ei = d_in[i];               break;
            case 8192:     W1 = (const float*)d_in[i]; break;
            case 16:       b1 = (const float*)d_in[i]; break;
            case 640:      W2 = (const float*)d_in[i]; break;
            case 40:       b2 = (const float*)d_in[i]; break;
            default: break;
        }
    }
    if (!x)  x  = (const float*)d_in[0];
    if (!ei) ei = d_in[1];
    if (!W1) W1 = (const float*)d_in[2];
    if (!b1) b1 = (const float*)d_in[3];
    if (!W2) W2 = (const float*)d_in[4];
    if (!b2) b2 = (const float*)d_in[5];

    const int N = N_NODES;
    const int E = E_EDGES;
    float* out = (float*)d_out;
    const unsigned* eiw = (const unsigned*)ei;

    // One-time side stream + fork/join events (not device memory).
    static cudaStream_t s1 = nullptr;
    static cudaEvent_t  evFork = nullptr, evScan = nullptr, evJoin = nullptr;
    if (!s1) {
        cudaStreamCreateWithFlags(&s1, cudaStreamNonBlocking);
        cudaEventCreateWithFlags(&evFork, cudaEventDisableTiming);
        cudaEventCreateWithFlags(&evScan, cudaEventDisableTiming);
        cudaEventCreateWithFlags(&evJoin, cudaEventDisableTiming);
    }

    // Fork: gemm1 (FMA-bound) on side stream, overlapping the CSR build.
    cudaEventRecord(evFork, 0);
    cudaStreamWaitEvent(s1, evFork, 0);
    k_gemm1<<<(N + G_ROWS - 1) / G_ROWS, 256, 0, s1>>>(x, W1, N);

    // CSR build chain on the main stream (scan is residency-independent).
    k_zero     <<<(N + 255) / 256, 256>>>(eiw, N);
    k_edge_prep<<<(E + 255) / 256, 256>>>(eiw, E);
    k_scanA    <<<NBLK, SCAN_B>>>(N);
    k_scanB    <<<1, 128>>>();
    k_scanC    <<<(N + 255) / 256, 256>>>(N, E);
    cudaEventRecord(evScan, 0);

    // Side stream: scale = raw * dinv (needs gemm + scan), overlaps fill.
    cudaStreamWaitEvent(s1, evScan, 0);
    k_scale<<<(N * 4 + 255) / 256, 256, 0, s1>>>(N);
    cudaEventRecord(evJoin, s1);

    // Main: fill, then join and aggregate.
    k_fill     <<<(E + 255) / 256, 256>>>(E);
    cudaStreamWaitEvent(0, evJoin, 0);
    k_gather1  <<<(N * 32 + 255) / 256, 256>>>(b1, N);
    k_gather2f <<<(N * 32 + 255) / 256, 256>>>(W2, b2, out, N);
}

// round 16
// speedup vs baseline: 1.5420x; 1.0170x over previous
#include <cuda_runtime.h>
#include <math.h>

#define N_NODES   100000
#define E_EDGES   3200000
#define FIN       512
#define F1        16
#define F2        40
#define SCAN_B    1024
#define NBLK      ((N_NODES + SCAN_B - 1) / SCAN_B)   // 98

// ---------------- scratch (no cudaMalloc allowed) ----------------
// Device symbols referenced ONLY from device code.
__device__ int    g_nz;                   // 0 => int64 edges, 1 => int32
__device__ int    g_cnt   [N_NODES];      // in-degree (excluding self loop)
__device__ int    g_fill  [N_NODES];      // CSR fill cursors
__device__ int    g_rowptr[N_NODES + 1];
__device__ int    g_blksum[128];
__device__ int    g_blkoff[128];
__device__ float  g_dinv  [N_NODES];
__device__ int    g_dst   [E_EDGES];
__device__ int    g_srcT  [E_EDGES];      // src staging
__device__ int    g_csrc  [E_EDGES];      // src ids grouped by dst (CSR)
__device__ float4 g_raw   [N_NODES * 4];  // x @ W1, unscaled (gemm output)
__device__ float4 g_hs    [N_NODES * 4];  // layer-1 features, pre-scaled by dinv
__device__ float4 g_hs2   [N_NODES * 4];  // layer-2 features, pre-scaled by dinv

// ---------------- K0: zero counters + dtype probe (fused) ----------------
__global__ void k_zero(const unsigned* __restrict__ I, int n) {
    int i = blockIdx.x * blockDim.x + threadIdx.x;
    if (i < n) { g_cnt[i] = 0; g_fill[i] = 0; }
    if (blockIdx.x == 0) {
        __shared__ int f;
        if (threadIdx.x == 0) f = 0;
        __syncthreads();
        // int64 little-endian ids < 2^17 => odd 32-bit words all zero.
        unsigned w = I[2 * (threadIdx.x * 1001) + 1]
                   | I[2 * (threadIdx.x * 4001) + 1];
        if (w != 0u) f = 1;        // benign race
        __syncthreads();
        if (threadIdx.x == 0) g_nz = f;
    }
}

// ---------------- K1: edges -> int32 staging, histogram in-degree ----------------
__global__ void k_edge_prep(const unsigned* __restrict__ I, int E) {
    int e = blockIdx.x * blockDim.x + threadIdx.x;
    if (e >= E) return;
    int s, d;
    if (g_nz == 0) {            // int64: take low words
        s = (int)I[2 * e];
        d = (int)I[2 * (E + e)];
    } else {                    // int32
        s = (int)I[e];
        d = (int)I[E + e];
    }
    if ((unsigned)s >= (unsigned)N_NODES) s = 0;   // defensive clamp
    if ((unsigned)d >= (unsigned)N_NODES) d = 0;
    g_srcT[e] = s;
    g_dst [e] = d;
    atomicAdd(&g_cnt[d], 1);    // unused return -> fire-and-forget RED
}

// ---------------- K2a/b/c: exclusive scan of g_cnt -> g_rowptr (deterministic) ----
__global__ void k_scanA(int n) {
    __shared__ int sm[SCAN_B];
    int t = threadIdx.x;
    int i = blockIdx.x * SCAN_B + t;
    int x = (i < n) ? g_cnt[i] : 0;
    sm[t] = x;
    __syncthreads();
    for (int off = 1; off < SCAN_B; off <<= 1) {
        int v = (t >= off) ? sm[t - off] : 0;
        __syncthreads();
        sm[t] += v;
        __syncthreads();
    }
    if (i < n) g_rowptr[i] = sm[t] - x;          // exclusive, per-block partial
    if (t == SCAN_B - 1) g_blksum[blockIdx.x] = sm[t];
}
__global__ void k_scanB() {
    __shared__ int sm[128];
    int t = threadIdx.x;
    int x = (t < NBLK) ? g_blksum[t] : 0;
    sm[t] = x;
    __syncthreads();
    for (int off = 1; off < 128; off <<= 1) {
        int v = (t >= off) ? sm[t - off] : 0;
        __syncthreads();
        sm[t] += v;
        __syncthreads();
    }
    g_blkoff[t] = sm[t] - x;                     // exclusive block offsets
}
__global__ void k_scanC(int n, int E) {
    int i = blockIdx.x * blockDim.x + threadIdx.x;
    if (i < n) {
        g_rowptr[i] += g_blkoff[i >> 10];
        g_dinv[i] = rsqrtf((float)(g_cnt[i] + 1));   // +1 self loop
    }
    if (i == 0) g_rowptr[n] = E;
}

// ---------------- K3: CSR fill (scalar int atomics only) ----------------
__global__ void k_fill(int E) {
    int e = blockIdx.x * blockDim.x + threadIdx.x;
    if (e >= E) return;
    int d = g_dst[e];
    int pos = g_rowptr[d] + atomicAdd(&g_fill[d], 1);
    if ((unsigned)pos >= (unsigned)E_EDGES) pos = 0;   // defensive clamp
    g_csrc[pos] = g_srcT[e];
}

// ---------------- K4: raw = x @ W1 (fp32, overlaps CSR build) ----------------
#define G_ROWS 128
#define G_KC   64
#define G_XS   68   // padded stride (floats)

__global__ __launch_bounds__(256) void k_gemm1(
    const float* __restrict__ x, const float* __restrict__ W1, int n)
{
    __shared__ float Wsm[G_KC * 16];        // 4 KB
    __shared__ float xsm[G_ROWS * G_XS];    // 34 KB
    const int tid  = threadIdx.x;
    const int row0 = blockIdx.x * G_ROWS;
    const int rg   = tid >> 2;              // 0..63 -> rows 2rg,2rg+1
    const int cg   = tid & 3;               // cols 4cg..4cg+3
    const int r0s  = (rg * 2) * G_XS;
    const int r1s  = r0s + G_XS;

    float4 acc0 = make_float4(0.f, 0.f, 0.f, 0.f);
    float4 acc1 = make_float4(0.f, 0.f, 0.f, 0.f);

    const int f4c = tid & 15;               // x-tile loader: 16 f4 cols
    const int rof = tid >> 4;               // 16 rows per pass

    for (int kc = 0; kc < FIN; kc += G_KC) {
        __syncthreads();
        ((float4*)Wsm)[tid] = ((const float4*)W1)[kc * 4 + tid];
        #pragma unroll
        for (int p = 0; p < 8; p++) {
            int r = p * 16 + rof;
            int gr = row0 + r; if (gr >= n) gr = n - 1;   // clamp (safe re-read)
            float4 v = *(const float4*)(x + (size_t)gr * FIN + kc + f4c * 4);
            *(float4*)(xsm + r * G_XS + f4c * 4) = v;
        }
        __syncthreads();
        #pragma unroll 16
        for (int k = 0; k < G_KC; k++) {
            float4 w4 = *(const float4*)(Wsm + k * 16 + cg * 4);
            float x0 = xsm[r0s + k];
            float x1 = xsm[r1s + k];
            acc0.x = fmaf(x0, w4.x, acc0.x);
            acc0.y = fmaf(x0, w4.y, acc0.y);
            acc0.z = fmaf(x0, w4.z, acc0.z);
            acc0.w = fmaf(x0, w4.w, acc0.w);
            acc1.x = fmaf(x1, w4.x, acc1.x);
            acc1.y = fmaf(x1, w4.y, acc1.y);
            acc1.z = fmaf(x1, w4.z, acc1.z);
            acc1.w = fmaf(x1, w4.w, acc1.w);
        }
    }
    int r0 = row0 + 2 * rg;
    if (r0 < n) g_raw[(size_t)r0 * 4 + cg] = acc0;
    int r1 = r0 + 1;
    if (r1 < n) g_raw[(size_t)r1 * 4 + cg] = acc1;
}

// ---------------- K4b: hs = raw * dinv[row] (side stream; overlaps fill) ----------------
__global__ void k_scale(int n) {
    int idx = blockIdx.x * blockDim.x + threadIdx.x;   // over n*4 quarters
    if (idx >= n * 4) return;
    float di = g_dinv[idx >> 2];
    float4 v = g_raw[idx];
    g_hs[idx] = make_float4(v.x * di, v.y * di, v.z * di, v.w * di);
}

// ---------------- K5: layer-1 CSR gather, 2-way ILP mainloop ----------------
// Warp per node. Lane = (edge slot eq 0..7) x (feature quarter q 0..3).
// Pair-iterations issue both csrc loads then both feature loads -> 2x MLP.
__global__ __launch_bounds__(256) void k_gather1(
    const float* __restrict__ b1, int n)
{
    int wid = (blockIdx.x * blockDim.x + threadIdx.x) >> 5;
    if (wid >= n) return;
    int lane = threadIdx.x & 31;
    int q  = lane & 3;
    int eq = lane >> 2;
    int e   = g_rowptr[wid] + eq;
    int end = g_rowptr[wid + 1];
    float4 acc = make_float4(0.f, 0.f, 0.f, 0.f);
    while (e + 8 < end) {
        int s0 = g_csrc[e];
        int s1 = g_csrc[e + 8];
        float4 v0 = g_hs[(size_t)s0 * 4 + q];
        float4 v1 = g_hs[(size_t)s1 * 4 + q];
        acc.x += v0.x + v1.x; acc.y += v0.y + v1.y;
        acc.z += v0.z + v1.z; acc.w += v0.w + v1.w;
        e += 16;
    }
    if (e < end) {
        int s = g_csrc[e];
        float4 v = g_hs[(size_t)s * 4 + q];
        acc.x += v.x; acc.y += v.y; acc.z += v.z; acc.w += v.w;
    }
    #pragma unroll
    for (int off = 4; off < 32; off <<= 1) {
        acc.x += __shfl_xor_sync(0xffffffffu, acc.x, off);
        acc.y += __shfl_xor_sync(0xffffffffu, acc.y, off);
        acc.z += __shfl_xor_sync(0xffffffffu, acc.z, off);
        acc.w += __shfl_xor_sync(0xffffffffu, acc.w, off);
    }
    if (eq == 0) {
        float4 self = g_hs[(size_t)wid * 4 + q];
        acc.x += self.x; acc.y += self.y; acc.z += self.z; acc.w += self.w;
        float di = g_dinv[wid];
        float4 b = ((const float4*)b1)[q];
        acc.x = fmaxf(fmaf(acc.x, di, b.x), 0.f) * di;
        acc.y = fmaxf(fmaf(acc.y, di, b.y), 0.f) * di;
        acc.z = fmaxf(fmaf(acc.z, di, b.z), 0.f) * di;
        acc.w = fmaxf(fmaf(acc.w, di, b.w), 0.f) * di;
        g_hs2[(size_t)wid * 4 + q] = acc;
    }
}

// ---------------- K6: fused layer-2 gather (2-way ILP) + W2 GEMM + log_softmax ----
__global__ __launch_bounds__(256) void k_gather2f(
    const float* __restrict__ W2, const float* __restrict__ b2,
    float* __restrict__ out, int n)
{
    __shared__ float Wsm[F1 * F2];      // 640 floats
    __shared__ float bsm[F2];
    int tid = threadIdx.x;
    for (int i = tid; i < F1 * F2; i += 256) Wsm[i] = W2[i];
    if (tid < F2) bsm[tid] = b2[tid];
    __syncthreads();

    int wid = (blockIdx.x * blockDim.x + tid) >> 5;
    if (wid >= n) return;
    int lane = tid & 31;
    int q  = lane & 3;
    int eq = lane >> 2;
    int e   = g_rowptr[wid] + eq;
    int end = g_rowptr[wid + 1];
    float4 acc = make_float4(0.f, 0.f, 0.f, 0.f);
    while (e + 8 < end) {
        int s0 = g_csrc[e];
        int s1 = g_csrc[e + 8];
        float4 v0 = g_hs2[(size_t)s0 * 4 + q];
        float4 v1 = g_hs2[(size_t)s1 * 4 + q];
        acc.x += v0.x + v1.x; acc.y += v0.y + v1.y;
        acc.z += v0.z + v1.z; acc.w += v0.w + v1.w;
        e += 16;
    }
    if (e < end) {
        int s = g_csrc[e];
        float4 v = g_hs2[(size_t)s * 4 + q];
        acc.x += v.x; acc.y += v.y; acc.z += v.z; acc.w += v.w;
    }
    #pragma unroll
    for (int off = 4; off < 32; off <<= 1) {
        acc.x += __shfl_xor_sync(0xffffffffu, acc.x, off);
        acc.y += __shfl_xor_sync(0xffffffffu, acc.y, off);
        acc.z += __shfl_xor_sync(0xffffffffu, acc.z, off);
        acc.w += __shfl_xor_sync(0xffffffffu, acc.w, off);
    }
    // Every lane holds the q-total for q = lane&3. Add self, scale by dinv.
    float4 self = g_hs2[(size_t)wid * 4 + q];
    float di = g_dinv[wid];
    acc.x = (acc.x + self.x) * di;
    acc.y = (acc.y + self.y) * di;
    acc.z = (acc.z + self.z) * di;
    acc.w = (acc.w + self.w) * di;

    // Broadcast the 16 features (lanes 0..3 hold q=0..3).
    float a[F1];
    #pragma unroll
    for (int qq = 0; qq < 4; qq++) {
        a[4 * qq + 0] = __shfl_sync(0xffffffffu, acc.x, qq);
        a[4 * qq + 1] = __shfl_sync(0xffffffffu, acc.y, qq);
        a[4 * qq + 2] = __shfl_sync(0xffffffffu, acc.z, qq);
        a[4 * qq + 3] = __shfl_sync(0xffffffffu, acc.w, qq);
    }

    // Lane computes output columns lane and lane+32 (latter only lanes 0..7).
    int j0 = lane, j1 = lane + 32;
    bool has1 = (j1 < F2);
    float o0 = bsm[j0];
    float o1 = has1 ? bsm[j1] : 0.f;
    #pragma unroll
    for (int k = 0; k < F1; k++) {
        o0 = fmaf(a[k], Wsm[k * F2 + j0], o0);
        if (has1) o1 = fmaf(a[k], Wsm[k * F2 + j1], o1);
    }
    float m = has1 ? fmaxf(o0, o1) : o0;
    #pragma unroll
    for (int off = 1; off < 32; off <<= 1)
        m = fmaxf(m, __shfl_xor_sync(0xffffffffu, m, off));
    float sum = expf(o0 - m) + (has1 ? expf(o1 - m) : 0.f);
    #pragma unroll
    for (int off = 1; off < 32; off <<= 1)
        sum += __shfl_xor_sync(0xffffffffu, sum, off);
    float lse = m + logf(sum);
    out[(size_t)wid * F2 + j0] = o0 - lse;
    if (has1) out[(size_t)wid * F2 + j1] = o1 - lse;
}

// ---------------- launch ----------------
extern "C" void kernel_launch(void* const* d_in, const int* in_sizes, int n_in,
                              void* d_out, int out_size) {
    // Identify inputs by element count (immune to metadata ordering):
    const float* x  = nullptr; const void* ei = nullptr;
    const float* W1 = nullptr; const float* b1 = nullptr;
    const float* W2 = nullptr; const float* b2 = nullptr;
    for (int i = 0; i < n_in; i++) {
        switch (in_sizes[i]) {
            case 51200000: x  = (const float*)d_in[i]; break;
            case 6400000:  ei = d_in[i];               break;
            case 8192:     W1 = (const float*)d_in[i]; break;
            case 16:       b1 = (const float*)d_in[i]; break;
            case 640:      W2 = (const float*)d_in[i]; break;
            case 40:       b2 = (const float*)d_in[i]; break;
            default: break;
        }
    }
    if (!x)  x  = (const float*)d_in[0];
    if (!ei) ei = d_in[1];
    if (!W1) W1 = (const float*)d_in[2];
    if (!b1) b1 = (const float*)d_in[3];
    if (!W2) W2 = (const float*)d_in[4];
    if (!b2) b2 = (const float*)d_in[5];

    const int N = N_NODES;
    const int E = E_EDGES;
    float* out = (float*)d_out;
    const unsigned* eiw = (const unsigned*)ei;

    // One-time side stream + fork/join events (not device memory).
    static cudaStream_t s1 = nullptr;
    static cudaEvent_t  evFork = nullptr, evScan = nullptr, evJoin = nullptr;
    if (!s1) {
        cudaStreamCreateWithFlags(&s1, cudaStreamNonBlocking);
        cudaEventCreateWithFlags(&evFork, cudaEventDisableTiming);
        cudaEventCreateWithFlags(&evScan, cudaEventDisableTiming);
        cudaEventCreateWithFlags(&evJoin, cudaEventDisableTiming);
    }

    // Fork: gemm1 (FMA-bound) on side stream, overlapping the CSR build.
    cudaEventRecord(evFork, 0);
    cudaStreamWaitEvent(s1, evFork, 0);
    k_gemm1<<<(N + G_ROWS - 1) / G_ROWS, 256, 0, s1>>>(x, W1, N);

    // CSR build chain on the main stream (scan is residency-independent).
    k_zero     <<<(N + 255) / 256, 256>>>(eiw, N);
    k_edge_prep<<<(E + 255) / 256, 256>>>(eiw, E);
    k_scanA    <<<NBLK, SCAN_B>>>(N);
    k_scanB    <<<1, 128>>>();
    k_scanC    <<<(N + 255) / 256, 256>>>(N, E);
    cudaEventRecord(evScan, 0);

    // Side stream: scale = raw * dinv (needs gemm + scan), overlaps fill.
    cudaStreamWaitEvent(s1, evScan, 0);
    k_scale<<<(N * 4 + 255) / 256, 256, 0, s1>>>(N);
    cudaEventRecord(evJoin, s1);

    // Main: fill, then join and aggregate.
    k_fill     <<<(E + 255) / 256, 256>>>(E);
    cudaStreamWaitEvent(0, evJoin, 0);
    k_gather1  <<<(N * 32 + 255) / 256, 256>>>(b1, N);
    k_gather2f <<<(N * 32 + 255) / 256, 256>>>(W2, b2, out, N);
}